// round 9
// baseline (speedup 1.0000x reference)
#include <cuda_runtime.h>

#define BB 16
#define SS 4096
#define HH 16
#define EE 64
#define SDIM 64
#define NW 127

// Scratch (device globals — no allocation allowed in kernel_launch)
__device__ float g_vs4[4*BB*HH*SDIM*EE]; // [q][b][h][j][e] partial column sums
__device__ float g_us[BB*HH*SDIM*EE];    // [b][h][i][e]    row sums (complete)
__device__ float g_rv[BB*SDIM*HH*EE];    // [b][k][h][e]    RxV
__device__ float g_ru[BB*SDIM*HH*EE];    // [b][k][h][e]    RxU
__device__ float g_zc[HH*SDIM];          // [h][k]          z conv (x64)
__device__ int   g_cnt_reduce[BB];       // 64 arrivals per batch
__device__ int   g_cnt_conv[BB];         // 32 arrivals per batch

struct SRed  { float4 stage[2][8*8*16]; };                       // 32KB
struct SConv { float vs[SDIM*EE]; float us[SDIM*EE];
               float w[NW+1]; float o[SDIM]; };                  // ~32.8KB
struct SZ    { float zc[HH*SDIM]; };

union SMem { SRed r; SConv c; SZ z; };

__global__ void k_zero() {
    int t = threadIdx.x;
    if (t < BB) { g_cnt_reduce[t] = 0; g_cnt_conv[t] = 0; }
}

__device__ __forceinline__ void wait_cnt(int* p, int target, int t) {
    if (t == 0) {
        while (*(volatile int*)p < target) __nanosleep(128);
    }
    __syncthreads();
}

__device__ __forceinline__ void signal_cnt(int* p, int t) {
    __threadfence();
    __syncthreads();
    if (t == 0) atomicAdd(p, 1);
}

// Interleaved software-pipeline schedule. Stage s (s=0..17) contains:
//   reduce(batch s)  x64   (s<16)
//   conv(batch s-1)  x32   (1<=s<=16)
//   z                x16   (s==2)
//   out(batch s-2)   x64   (2<=s<=17)
// Blocks dispatch in bid order, so the resident window always mixes
// read-units (reduce) with write-units (out) -> HBM read/write overlap,
// and consumers trail their producers by ~1 stage (short spins only while
// the pipeline fills). Total units = 1024+512+16+1024 = 2576.
__device__ __forceinline__ void decode(int bid, int& role, int& idx) {
    int T = bid;
    #pragma unroll 1
    for (int s = 0; s < 18; ++s) {
        int nred  = (s < 16) ? 64 : 0;
        int nconv = (s >= 1 && s <= 16) ? 32 : 0;
        int nz    = (s == 2) ? 16 : 0;
        int nout  = (s >= 2) ? 64 : 0;
        int tot = nred + nconv + nz + nout;
        if (T < tot) {
            if (T < nred)  { role = 0; idx = s*64 + T; return; }
            T -= nred;
            if (T < nconv) { role = 1; idx = (s-1)*32 + T; return; }
            T -= nconv;
            if (T < nz)    { role = 3; idx = T; return; }
            T -= nz;
            role = 2; idx = (s-2)*64 + T; return;
        }
        T -= tot;
    }
    role = -1; idx = 0;
}

// ---------------------------------------------------------------------------
// Fused, pipeline-scheduled kernel. 64-reg cap -> 4 blocks/SM.
// ---------------------------------------------------------------------------
__global__ __launch_bounds__(256, 4) void k_fused(const float* __restrict__ v,
                                                  const float* __restrict__ w,
                                                  const float* __restrict__ o_,
                                                  float* __restrict__ out) {
    __shared__ SMem sm;
    int t = threadIdx.x;
    int role, uidx;
    decode(blockIdx.x, role, uidx);

    if (role == 0) {
        // ----- reduce: unit = (bh, q); 16 i-rows of one (b,h) plane -----
        int bh = uidx >> 2, q = uidx & 3;
        int b = bh >> 4, h = bh & 15;
        int e4 = t & 15, sub = (t >> 4) & 1, wpw = t >> 5;   // 8 warps

        const float4* v4 = reinterpret_cast<const float4*>(v)
                         + (size_t)b*SS*(HH*EE/4) + h*(EE/4) + e4;

        int i = q*16 + wpw*2 + sub;      // this thread's i-row
        float4 crow = make_float4(0.f,0.f,0.f,0.f);

        float* vs_dst = g_vs4 + (size_t)(q*BB*HH + bh)*SDIM*EE;

        #pragma unroll 1
        for (int jc = 0; jc < 8; ++jc) {
            float4 vloc[8];
            const float4* p0 = v4 + (size_t)(i*SDIM + jc*8)*(HH*EE/4);
            #pragma unroll
            for (int jj = 0; jj < 8; ++jj) {
                float4 a = __ldcs(p0 + (size_t)jj*(HH*EE/4));
                crow.x += a.x; crow.y += a.y; crow.z += a.z; crow.w += a.w;
                vloc[jj] = a;
            }
            #pragma unroll
            for (int jj = 0; jj < 8; ++jj) {
                vloc[jj].x += __shfl_down_sync(0xffffffffu, vloc[jj].x, 16);
                vloc[jj].y += __shfl_down_sync(0xffffffffu, vloc[jj].y, 16);
                vloc[jj].z += __shfl_down_sync(0xffffffffu, vloc[jj].z, 16);
                vloc[jj].w += __shfl_down_sync(0xffffffffu, vloc[jj].w, 16);
            }
            if (sub == 0) {
                #pragma unroll
                for (int jj = 0; jj < 8; ++jj)
                    sm.r.stage[jc & 1][(wpw*8 + jj)*16 + e4] = vloc[jj];
            }
            __syncthreads();

            bool lower = (t < 128);
            if (lower == ((jc & 1) == 0)) {
                int tt = t & 127;
                int jj = tt >> 4, ee = tt & 15;
                float4 s = sm.r.stage[jc & 1][jj*16 + ee];
                #pragma unroll
                for (int ww = 1; ww < 8; ++ww) {
                    float4 x = sm.r.stage[jc & 1][(ww*8 + jj)*16 + ee];
                    s.x += x.x; s.y += x.y; s.z += x.z; s.w += x.w;
                }
                reinterpret_cast<float4*>(vs_dst + (jc*8 + jj)*EE)[ee] = s;
            }
        }

        float4* us4 = reinterpret_cast<float4*>(g_us + (size_t)bh*SDIM*EE);
        us4[i*(EE/4) + e4] = crow;

        signal_cnt(&g_cnt_reduce[b], t);

    } else if (role == 1) {
        // ----- conv: unit = (bh, kh) half-k -----
        int bh = uidx >> 1, kh = uidx & 1;
        int b = bh >> 4, h = bh & 15;

        if (t < NW) sm.c.w[t] = w[h*NW + t];
        if (t >= 128 && t < 128 + SDIM) sm.c.o[t - 128] = o_[t - 128];

        wait_cnt(&g_cnt_reduce[b], 64, t);

        const size_t base = (size_t)bh*SDIM*EE;
        const size_t slice4 = (size_t)BB*HH*SDIM*EE/4;
        {
            const float4* p0 = reinterpret_cast<const float4*>(g_vs4 + base);
            const float4* pu = reinterpret_cast<const float4*>(g_us + base);
            float4* vsv = reinterpret_cast<float4*>(sm.c.vs);
            float4* usv = reinterpret_cast<float4*>(sm.c.us);
            #pragma unroll
            for (int r = 0; r < 4; ++r) {
                int idx = r*256 + t;
                float4 a = __ldcg(p0 + idx);
                float4 x = __ldcg(p0 + slice4 + idx);
                float4 y = __ldcg(p0 + 2*slice4 + idx);
                float4 zz = __ldcg(p0 + 3*slice4 + idx);
                vsv[idx] = make_float4(a.x+x.x+y.x+zz.x, a.y+x.y+y.y+zz.y,
                                       a.z+x.z+y.z+zz.z, a.w+x.w+y.w+zz.w);
                usv[idx] = __ldcg(pu + idx);
            }
        }
        __syncthreads();

        if (b == 0 && kh == 0 && t < SDIM) {
            float acc = 0.f;
            #pragma unroll
            for (int j = 0; j < SDIM; ++j) {
                int idx = t + 64 - j;
                if (idx > 126) idx -= 127;
                acc += sm.c.o[j] * sm.c.w[idx];
            }
            g_zc[h*SDIM + t] = acc * 64.f;
        }

        int e = t & 63, g = t >> 6;
        #pragma unroll 1
        for (int k = kh*32 + g; k < kh*32 + 32; k += 4) {
            float rv = 0.f, ru = 0.f;
            #pragma unroll
            for (int j = 0; j < SDIM; ++j) {
                int idx = k + 64 - j;            // [1,127]
                if (idx > 126) idx -= 127;
                float wk = sm.c.w[idx];
                rv += sm.c.vs[j*EE + e] * wk;
                ru += sm.c.us[j*EE + e] * wk;
            }
            size_t o = ((size_t)(b*SDIM + k)*HH + h)*EE + e;
            g_rv[o] = rv;
            g_ru[o] = ru;
        }

        signal_cnt(&g_cnt_conv[b], t);

    } else if (role == 2) {
        // ----- out: unit = (b, itile, jt) 8i x 8j tile of pbv -----
        int b = uidx >> 6;
        int itile = (uidx >> 3) & 7;
        int jt = uidx & 7;

        wait_cnt(&g_cnt_conv[b], 32, t);

        const float4* rub = reinterpret_cast<const float4*>(g_ru + (size_t)b*SDIM*HH*EE)
                          + (size_t)itile*8*(HH*EE/4) + t;
        const float4* rvb = reinterpret_cast<const float4*>(g_rv + (size_t)b*SDIM*HH*EE)
                          + (size_t)jt*8*(HH*EE/4) + t;
        float4* ob = reinterpret_cast<float4*>(out + (size_t)b*SS*HH*EE)
                   + ((size_t)itile*8*SDIM + jt*8)*(HH*EE/4) + t;

        float4 uu[8];
        #pragma unroll
        for (int m = 0; m < 8; ++m)
            uu[m] = __ldcg(rub + m*(HH*EE/4));

        #pragma unroll 1
        for (int jj = 0; jj < 8; ++jj) {
            float4 vv = __ldcg(rvb + jj*(HH*EE/4));
            #pragma unroll
            for (int m = 0; m < 8; ++m) {
                float4 o;
                o.x = vv.x + uu[m].x; o.y = vv.y + uu[m].y;
                o.z = vv.z + uu[m].z; o.w = vv.w + uu[m].w;
                __stcs(ob + ((size_t)m*SDIM + jj)*(HH*EE/4), o);
            }
        }

    } else {
        // ----- z: z_pb output from g_zc -----
        int zi = uidx;                  // 0..15 -> i = zi*4 .. +3
        wait_cnt(&g_cnt_conv[0], 32, t);

        for (int idx = t; idx < HH*SDIM; idx += 256)
            sm.z.zc[idx] = __ldcg((const float*)g_zc + idx);
        __syncthreads();

        float* o2 = out + (size_t)BB*SS*HH*EE;
        #pragma unroll
        for (int r = 0; r < 4; ++r) {
            int i = zi*4 + r;
            #pragma unroll
            for (int it = 0; it < 4; ++it) {
                int idx = it*256 + t;
                int j = idx >> 4, h = idx & 15;
                o2[(size_t)i*1024 + idx] = sm.z.zc[h*SDIM + j] + sm.z.zc[h*SDIM + i];
            }
        }
    }
}

extern "C" void kernel_launch(void* const* d_in, const int* in_sizes, int n_in,
                              void* d_out, int out_size) {
    const float* v  = (const float*)d_in[0];
    const float* w  = (const float*)d_in[1];
    const float* o_ = (const float*)d_in[2];
    float* out = (float*)d_out;

    k_zero <<<1, 32>>>();
    k_fused<<<2576, 256>>>(v, w, o_, out);
}

// round 10
// speedup vs baseline: 1.1476x; 1.1476x over previous
#include <cuda_runtime.h>

#define BB 16
#define SS 4096
#define HH 16
#define EE 64
#define SDIM 64
#define NW 127

// Scratch (device globals — no allocation allowed in kernel_launch)
__device__ float g_vs2[2*BB*HH*SDIM*EE]; // [half][b][h][j][e] partial column sums
__device__ float g_us[BB*HH*SDIM*EE];    // [b][h][i][e]       row sums
__device__ float g_rv[BB*SDIM*HH*EE];    // [b][k][h][e]       RxV
__device__ float g_ru[BB*SDIM*HH*EE];    // [b][k][h][e]       RxU
__device__ float g_zc[HH*SDIM];          // [h][k]             z conv (x64)
__device__ int   g_tk[BB*HH];            // per-(b,h) ticket (2 arrivals)

struct SRed  { float4 stage[2][8*4*16]; };                       // 16KB
struct SConv { float vs[SDIM*EE]; float us[SDIM*EE];
               float w[NW+1]; float o[SDIM]; };                  // ~33KB
union SMem { SRed r; SConv c; };

__global__ void k_zero() {
    int t = threadIdx.x + blockIdx.x*256;
    if (t < BB*HH) g_tk[t] = 0;
}

// ---------------------------------------------------------------------------
// Kernel 1: reduce + ticket-folded conv.
// Grid 512: (bh, half). Block reduces 32 i-rows of plane (b,h): per-thread
// 2 i-rows, j in chunks of 4 (vloc[4] -> ~48 regs -> 5 blocks/SM), shfl
// half-warp combine, double-buffered smem stage with alternating reducer
// halves (1 barrier/chunk; non-reducing half issues next chunk's loads).
// Then each block tickets g_tk[bh]; the SECOND arriver immediately runs the
// 64-tap circular convolutions for that (b,h) (zero spin-waiting) and, for
// b==0, the z conv. Conv executions overlap other blocks' reduce streams.
// ---------------------------------------------------------------------------
__global__ __launch_bounds__(256, 5) void k_reduce(const float* __restrict__ v,
                                                   const float* __restrict__ w,
                                                   const float* __restrict__ o_) {
    __shared__ SMem sm;
    __shared__ int s_win;
    int bid = blockIdx.x;
    int bh = bid >> 1, half = bid & 1;
    int b = bh >> 4, h = bh & 15;
    int t = threadIdx.x;
    int e4 = t & 15, sub = (t >> 4) & 1, wpw = t >> 5;   // 8 warps

    const float4* v4 = reinterpret_cast<const float4*>(v)
                     + (size_t)b*SS*(HH*EE/4) + h*(EE/4) + e4;

    int i0 = half*32 + wpw*4 + sub*2;
    float4 crow0 = make_float4(0.f,0.f,0.f,0.f);
    float4 crow1 = make_float4(0.f,0.f,0.f,0.f);

    float* vs_dst = g_vs2 + (size_t)(half*BB*HH + bh)*SDIM*EE;

    #pragma unroll 1
    for (int jc = 0; jc < 16; ++jc) {
        float4 vloc[4];
        const float4* p0 = v4 + (size_t)(i0*SDIM + jc*4)*(HH*EE/4);
        const float4* p1 = p0 + (size_t)SDIM*(HH*EE/4);
        #pragma unroll
        for (int jj = 0; jj < 4; ++jj) {
            float4 a = __ldcs(p0 + (size_t)jj*(HH*EE/4));
            float4 c = __ldcs(p1 + (size_t)jj*(HH*EE/4));
            crow0.x += a.x; crow0.y += a.y; crow0.z += a.z; crow0.w += a.w;
            crow1.x += c.x; crow1.y += c.y; crow1.z += c.z; crow1.w += c.w;
            vloc[jj] = make_float4(a.x + c.x, a.y + c.y, a.z + c.z, a.w + c.w);
        }
        // combine the two half-warps (different i-pairs, same j/e)
        #pragma unroll
        for (int jj = 0; jj < 4; ++jj) {
            vloc[jj].x += __shfl_down_sync(0xffffffffu, vloc[jj].x, 16);
            vloc[jj].y += __shfl_down_sync(0xffffffffu, vloc[jj].y, 16);
            vloc[jj].z += __shfl_down_sync(0xffffffffu, vloc[jj].z, 16);
            vloc[jj].w += __shfl_down_sync(0xffffffffu, vloc[jj].w, 16);
        }
        if (sub == 0) {
            #pragma unroll
            for (int jj = 0; jj < 4; ++jj)
                sm.r.stage[jc & 1][(wpw*4 + jj)*16 + e4] = vloc[jj];
        }
        __syncthreads();

        // alternate halves: the other half proceeds to next chunk's loads
        bool lower = (t < 128);
        if (lower == ((jc & 1) == 0)) {
            int tt = t & 127;
            if (tt < 64) {
                int jj = tt >> 4, ee = tt & 15;
                float4 s = sm.r.stage[jc & 1][jj*16 + ee];
                #pragma unroll
                for (int ww = 1; ww < 8; ++ww) {
                    float4 x = sm.r.stage[jc & 1][(ww*4 + jj)*16 + ee];
                    s.x += x.x; s.y += x.y; s.z += x.z; s.w += x.w;
                }
                reinterpret_cast<float4*>(vs_dst + (jc*4 + jj)*EE)[ee] = s;
            }
        }
    }

    // Row sums (complete for this thread's 2 i-rows).
    float4* us4 = reinterpret_cast<float4*>(g_us + (size_t)bh*SDIM*EE);
    us4[(i0    )*(EE/4) + e4] = crow0;
    us4[(i0 + 1)*(EE/4) + e4] = crow1;

    // ----- ticket: second arriver runs this (b,h)'s conv, no spinning -----
    __threadfence();
    __syncthreads();
    if (t == 0) s_win = atomicAdd(&g_tk[bh], 1);
    __syncthreads();
    if (s_win != 1) return;
    __threadfence();   // acquire: make the other block's writes visible

    // conv: load inputs into the (now dead) stage area's union view
    if (t < NW) sm.c.w[t] = w[h*NW + t];
    if (t >= 128 && t < 128 + SDIM) sm.c.o[t - 128] = o_[t - 128];
    {
        const size_t base = (size_t)bh*SDIM*EE;
        const size_t slice4 = (size_t)BB*HH*SDIM*EE/4;
        const float4* p0 = reinterpret_cast<const float4*>(g_vs2 + base);
        const float4* pu = reinterpret_cast<const float4*>(g_us + base);
        float4* vsv = reinterpret_cast<float4*>(sm.c.vs);
        float4* usv = reinterpret_cast<float4*>(sm.c.us);
        #pragma unroll
        for (int r = 0; r < 4; ++r) {
            int idx = r*256 + t;
            float4 a = __ldcg(p0 + idx);
            float4 x = __ldcg(p0 + slice4 + idx);
            vsv[idx] = make_float4(a.x+x.x, a.y+x.y, a.z+x.z, a.w+x.w);
            usv[idx] = __ldcg(pu + idx);
        }
    }
    __syncthreads();

    if (b == 0 && t < SDIM) {
        float acc = 0.f;
        #pragma unroll
        for (int j = 0; j < SDIM; ++j) {
            int idx = t + 64 - j;
            if (idx > 126) idx -= 127;
            acc += sm.c.o[j] * sm.c.w[idx];
        }
        g_zc[h*SDIM + t] = acc * 64.f;
    }

    int e = t & 63, g = t >> 6;
    #pragma unroll 1
    for (int k = g; k < SDIM; k += 4) {
        float rv = 0.f, ru = 0.f;
        #pragma unroll
        for (int j = 0; j < SDIM; ++j) {
            int idx = k + 64 - j;            // [1,127]
            if (idx > 126) idx -= 127;
            float wk = sm.c.w[idx];
            rv += sm.c.vs[j*EE + e] * wk;
            ru += sm.c.us[j*EE + e] * wk;
        }
        size_t o = ((size_t)(b*SDIM + k)*HH + h)*EE + e;
        g_rv[o] = rv;
        g_ru[o] = ru;
    }
}

// ---------------------------------------------------------------------------
// Kernel 2: pbv[b, i*64+j, h, e] = RxV[...,j] + RxU[...,i].
// Blocks 0..1023: 8i x 8j tile; RxU rows in registers, each RxV row from L2
// serves 8 output rows; streaming stores for the 256MB write.
// Blocks 1024..1039: z_pb output from g_zc.
// ---------------------------------------------------------------------------
__global__ __launch_bounds__(256) void k_out(float* __restrict__ out) {
    int blk = blockIdx.x;
    int t = threadIdx.x;

    if (blk < 1024) {
        int b = blk >> 6;
        int itile = (blk >> 3) & 7;
        int jt = blk & 7;

        const float4* rub = reinterpret_cast<const float4*>(g_ru + (size_t)b*SDIM*HH*EE)
                          + (size_t)itile*8*(HH*EE/4) + t;
        const float4* rvb = reinterpret_cast<const float4*>(g_rv + (size_t)b*SDIM*HH*EE)
                          + (size_t)jt*8*(HH*EE/4) + t;
        float4* ob = reinterpret_cast<float4*>(out + (size_t)b*SS*HH*EE)
                   + ((size_t)itile*8*SDIM + jt*8)*(HH*EE/4) + t;

        float4 uu[8];
        #pragma unroll
        for (int m = 0; m < 8; ++m)
            uu[m] = __ldg(rub + m*(HH*EE/4));

        #pragma unroll 1
        for (int jj = 0; jj < 8; ++jj) {
            float4 vv = __ldg(rvb + jj*(HH*EE/4));
            #pragma unroll
            for (int m = 0; m < 8; ++m) {
                float4 o;
                o.x = vv.x + uu[m].x; o.y = vv.y + uu[m].y;
                o.z = vv.z + uu[m].z; o.w = vv.w + uu[m].w;
                __stcs(ob + ((size_t)m*SDIM + jj)*(HH*EE/4), o);
            }
        }
    } else {
        int zi = blk - 1024;            // 0..15 -> i = zi*4 .. +3
        __shared__ float zc[HH*SDIM];
        for (int idx = t; idx < HH*SDIM; idx += 256) zc[idx] = g_zc[idx];
        __syncthreads();

        float* o2 = out + (size_t)BB*SS*HH*EE;
        #pragma unroll
        for (int r = 0; r < 4; ++r) {
            int i = zi*4 + r;
            #pragma unroll
            for (int it = 0; it < 4; ++it) {
                int idx = it*256 + t;
                int j = idx >> 4, h = idx & 15;
                o2[(size_t)i*1024 + idx] = zc[h*SDIM + j] + zc[h*SDIM + i];
            }
        }
    }
}

extern "C" void kernel_launch(void* const* d_in, const int* in_sizes, int n_in,
                              void* d_out, int out_size) {
    const float* v  = (const float*)d_in[0];
    const float* w  = (const float*)d_in[1];
    const float* o_ = (const float*)d_in[2];
    float* out = (float*)d_out;

    k_zero  <<<1, 256>>>();
    k_reduce<<<BB*HH*2, 256>>>(v, w, o_);
    k_out   <<<1024 + 16, 256>>>(out);
}

// round 11
// speedup vs baseline: 1.6888x; 1.4716x over previous
#include <cuda_runtime.h>

#define BB 16
#define SS 4096
#define HH 16
#define EE 64
#define SDIM 64
#define NW 127

// Scratch (device globals — no allocation allowed in kernel_launch)
__device__ float g_vs2[2*BB*HH*SDIM*EE]; // [half][b][h][j][e] partial column sums
__device__ float g_us[BB*HH*SDIM*EE];    // [b][h][i][e]       row sums (complete)
__device__ float g_rv[BB*SDIM*HH*EE];    // [b][k][h][e]       RxV
__device__ float g_ru[BB*SDIM*HH*EE];    // [b][k][h][e]       RxU
__device__ float g_zc[HH*SDIM];          // [h][k]             z conv (x64)

// ---------------------------------------------------------------------------
// Kernel 1: row/column sums of v viewed as (b, i, j, h, e), s = i*64+j.
// Grid = 512: (bh, half). Block covers 32 i. Warp w owns i = half*32+w*4+sub*2
// +{0,1}. j in chunks of 4 (vloc[4] -> ~48 regs -> 5 blocks/SM via
// launch_bounds). Half-warp pairs combine column partials via shfl_down(16);
// double-buffered 8KB stage, ONE barrier per chunk, reducer half alternates
// so the other half issues the next chunk's LDG.128s immediately.
// ---------------------------------------------------------------------------
__global__ __launch_bounds__(256, 5) void k_reduce(const float* __restrict__ v) {
    int bid = blockIdx.x;
    int bh = bid >> 1, half = bid & 1;
    int b = bh >> 4, h = bh & 15;
    int t = threadIdx.x;
    int e4 = t & 15, sub = (t >> 4) & 1, w = t >> 5;

    __shared__ float4 stage[2][8*4*16];   // [buf][w*4+jj][e4]  2 x 8KB

    const float4* v4 = reinterpret_cast<const float4*>(v)
                     + (size_t)b*SS*(HH*EE/4) + h*(EE/4) + e4;

    int i0 = half*32 + w*4 + sub*2;
    float4 crow0 = make_float4(0.f,0.f,0.f,0.f);
    float4 crow1 = make_float4(0.f,0.f,0.f,0.f);

    float* vs_dst = g_vs2 + (size_t)(half*BB*HH + bh)*SDIM*EE;

    #pragma unroll 1
    for (int jc = 0; jc < 16; ++jc) {
        float4 vloc[4];
        const float4* p0 = v4 + (size_t)(i0*SDIM + jc*4)*(HH*EE/4);
        const float4* p1 = p0 + (size_t)SDIM*(HH*EE/4);
        #pragma unroll
        for (int jj = 0; jj < 4; ++jj) {
            float4 a = __ldcs(p0 + (size_t)jj*(HH*EE/4));
            float4 c = __ldcs(p1 + (size_t)jj*(HH*EE/4));
            crow0.x += a.x; crow0.y += a.y; crow0.z += a.z; crow0.w += a.w;
            crow1.x += c.x; crow1.y += c.y; crow1.z += c.z; crow1.w += c.w;
            vloc[jj] = make_float4(a.x + c.x, a.y + c.y, a.z + c.z, a.w + c.w);
        }
        // combine the two half-warps (sub 0/1 hold different i-pairs, same j/e)
        #pragma unroll
        for (int jj = 0; jj < 4; ++jj) {
            vloc[jj].x += __shfl_down_sync(0xffffffffu, vloc[jj].x, 16);
            vloc[jj].y += __shfl_down_sync(0xffffffffu, vloc[jj].y, 16);
            vloc[jj].z += __shfl_down_sync(0xffffffffu, vloc[jj].z, 16);
            vloc[jj].w += __shfl_down_sync(0xffffffffu, vloc[jj].w, 16);
        }
        if (sub == 0) {
            #pragma unroll
            for (int jj = 0; jj < 4; ++jj)
                stage[jc & 1][(w*4 + jj)*16 + e4] = vloc[jj];
        }
        __syncthreads();

        // Alternate which half reduces; the other half issues next-chunk loads.
        bool lower = (t < 128);
        if (lower == ((jc & 1) == 0)) {
            int tt = t & 127;
            if (tt < 64) {
                int jj = tt >> 4, ee = tt & 15;
                float4 s = stage[jc & 1][jj*16 + ee];
                #pragma unroll
                for (int ww = 1; ww < 8; ++ww) {
                    float4 x = stage[jc & 1][(ww*4 + jj)*16 + ee];
                    s.x += x.x; s.y += x.y; s.z += x.z; s.w += x.w;
                }
                reinterpret_cast<float4*>(vs_dst + (jc*4 + jj)*EE)[ee] = s;
            }
        }
    }

    // Row sums (complete: thread covered all 64 j for its 2 i's).
    float4* us4 = reinterpret_cast<float4*>(g_us + (size_t)bh*SDIM*EE);
    us4[(i0    )*(EE/4) + e4] = crow0;
    us4[(i0 + 1)*(EE/4) + e4] = crow1;
}

// ---------------------------------------------------------------------------
// Kernel 2: 64-tap circular convolutions. Grid 512: 2 blocks per (b,h), each
// covering half the k range. Merges the 2 partial column-sum slices with
// float4 loads. b==0,kh==0 blocks also compute zc.
// ---------------------------------------------------------------------------
__global__ __launch_bounds__(256) void k_conv(const float* __restrict__ w,
                                              const float* __restrict__ o_) {
    int blk = blockIdx.x;
    int bh = blk >> 1, kh = blk & 1;
    int b = bh >> 4, h = bh & 15;
    int t = threadIdx.x;

    __shared__ float vs_s[SDIM*EE];
    __shared__ float us_s[SDIM*EE];
    __shared__ float w_s[NW];
    __shared__ float o_s[SDIM];

    const size_t base = (size_t)bh*SDIM*EE;
    const size_t slice4 = (size_t)BB*HH*SDIM*EE/4;
    {
        const float4* pa = reinterpret_cast<const float4*>(g_vs2 + base);
        const float4* pu = reinterpret_cast<const float4*>(g_us + base);
        float4* vsv = reinterpret_cast<float4*>(vs_s);
        float4* usv = reinterpret_cast<float4*>(us_s);
        #pragma unroll
        for (int r = 0; r < 4; ++r) {
            int idx = r*256 + t;
            float4 x = __ldg(pa + idx), y = __ldg(pa + slice4 + idx);
            vsv[idx] = make_float4(x.x+y.x, x.y+y.y, x.z+y.z, x.w+y.w);
            usv[idx] = __ldg(pu + idx);
        }
    }
    if (t < NW) w_s[t] = w[h*NW + t];
    if (t >= 128 && t < 128 + SDIM) o_s[t - 128] = o_[t - 128];
    __syncthreads();

    if (b == 0 && kh == 0 && t < SDIM) {
        float acc = 0.f;
        #pragma unroll
        for (int j = 0; j < SDIM; ++j) {
            int idx = t + 64 - j;
            if (idx > 126) idx -= 127;
            acc += o_s[j] * w_s[idx];
        }
        g_zc[h*SDIM + t] = acc * 64.f;
    }

    int e = t & 63, g = t >> 6;
    #pragma unroll 1
    for (int k = kh*32 + g; k < kh*32 + 32; k += 4) {
        float rv = 0.f, ru = 0.f;
        #pragma unroll
        for (int j = 0; j < SDIM; ++j) {
            int idx = k + 64 - j;            // range [1,127]
            if (idx > 126) idx -= 127;       // 127 -> 0
            float wk = w_s[idx];
            rv += vs_s[j*EE + e] * wk;
            ru += us_s[j*EE + e] * wk;
        }
        size_t o = ((size_t)(b*SDIM + k)*HH + h)*EE + e;
        g_rv[o] = rv;
        g_ru[o] = ru;
    }
}

// ---------------------------------------------------------------------------
// Kernel 3: pbv[b, i*64+j, h, e] = RxV[...,j] + RxU[...,i].
// Blocks 0..511: tile 8 i x 16 j; RxU rows in registers (each read once per
// 2 j-tiles -> ru L2 reads halve vs 8x8), each RxV row from L2 serves 8
// output rows; streaming stores for the 256MB write.
// Blocks 512..527: z_pb output from g_zc.
// ---------------------------------------------------------------------------
__global__ __launch_bounds__(256) void k_out(float* __restrict__ out) {
    int blk = blockIdx.x;
    int t = threadIdx.x;

    if (blk < 512) {
        int b = blk >> 5;
        int itile = (blk >> 2) & 7;     // i = itile*8 .. +7
        int jt = blk & 3;               // j = jt*16 .. +15

        const float4* rub = reinterpret_cast<const float4*>(g_ru + (size_t)b*SDIM*HH*EE)
                          + (size_t)itile*8*(HH*EE/4) + t;
        const float4* rvb = reinterpret_cast<const float4*>(g_rv + (size_t)b*SDIM*HH*EE)
                          + (size_t)jt*16*(HH*EE/4) + t;
        float4* ob = reinterpret_cast<float4*>(out + (size_t)b*SS*HH*EE)
                   + ((size_t)itile*8*SDIM + jt*16)*(HH*EE/4) + t;

        float4 uu[8];
        #pragma unroll
        for (int m = 0; m < 8; ++m)
            uu[m] = __ldg(rub + m*(HH*EE/4));

        #pragma unroll 1
        for (int jj = 0; jj < 16; ++jj) {
            float4 vv = __ldg(rvb + jj*(HH*EE/4));
            #pragma unroll
            for (int m = 0; m < 8; ++m) {
                float4 o;
                o.x = vv.x + uu[m].x; o.y = vv.y + uu[m].y;
                o.z = vv.z + uu[m].z; o.w = vv.w + uu[m].w;
                __stcs(ob + ((size_t)m*SDIM + jj)*(HH*EE/4), o);
            }
        }
    } else {
        int zi = blk - 512;             // 0..15 -> i = zi*4 .. +3
        __shared__ float zc[HH*SDIM];
        for (int idx = t; idx < HH*SDIM; idx += 256) zc[idx] = g_zc[idx];
        __syncthreads();

        float* o2 = out + (size_t)BB*SS*HH*EE;
        #pragma unroll
        for (int r = 0; r < 4; ++r) {
            int i = zi*4 + r;
            #pragma unroll
            for (int it = 0; it < 4; ++it) {
                int idx = it*256 + t;
                int j = idx >> 4, h = idx & 15;
                o2[(size_t)i*1024 + idx] = zc[h*SDIM + j] + zc[h*SDIM + i];
            }
        }
    }
}

extern "C" void kernel_launch(void* const* d_in, const int* in_sizes, int n_in,
                              void* d_out, int out_size) {
    const float* v  = (const float*)d_in[0];
    const float* w  = (const float*)d_in[1];
    const float* o_ = (const float*)d_in[2];
    float* out = (float*)d_out;

    k_reduce<<<BB*HH*2, 256>>>(v);
    k_conv  <<<BB*HH*2, 256>>>(w, o_);
    k_out   <<<512 + 16, 256>>>(out);
}